// round 8
// baseline (speedup 1.0000x reference)
#include <cuda_runtime.h>
#include <cstdint>

// RealEmbedding: out[bt, i*C_OUT + j] = x[bt, i] * W[i, j] + b[i, j]
// B=64, T=512, C_IN=128, C_OUT=16  -> rows = 32768, row_out = 2048 floats.
//
// Pure HBM-write-bound (256 MB out, 16 MB in). Strategy:
//  - thread (i, j4) keeps W[i, j4*4..+3] and b[i, j4*4..+3] in registers,
//    grid-strides over rows. 512 threads = one full output row per iter.
//  - STG.128 stores, warp-contiguous 512B. x read once per row per quad-group
//    (same 32B sector for the 4 threads sharing a channel -> L1 broadcast).

static constexpr int C_IN    = 128;
static constexpr int C_OUT   = 16;
static constexpr int ROW_OUT = C_IN * C_OUT;   // 2048
static constexpr int TPB     = 512;            // C_IN * (C_OUT/4)

__global__ __launch_bounds__(TPB, 4)
void real_embedding_kernel(const float* __restrict__ x,
                           const float* __restrict__ W,
                           const float* __restrict__ Bv,
                           float* __restrict__ out,
                           int n_rows)
{
    const int tid = threadIdx.x;        // 0..511
    const int i   = tid >> 2;           // input channel 0..127
    const int j4  = tid & 3;            // which float4 of the 16 outputs

    // Per-thread constants: one float4 of W and b, loaded once.
    const float4 w4 = __ldg(reinterpret_cast<const float4*>(W  + i * C_OUT + j4 * 4));
    const float4 b4 = __ldg(reinterpret_cast<const float4*>(Bv + i * C_OUT + j4 * 4));

    const int out_off = i * C_OUT + j4 * 4;

    for (int row = blockIdx.x; row < n_rows; row += gridDim.x) {
        const float xv = __ldg(x + (size_t)row * C_IN + i);
        float4 o;
        o.x = fmaf(xv, w4.x, b4.x);
        o.y = fmaf(xv, w4.y, b4.y);
        o.z = fmaf(xv, w4.z, b4.z);
        o.w = fmaf(xv, w4.w, b4.w);
        *reinterpret_cast<float4*>(out + (size_t)row * ROW_OUT + out_off) = o;
    }
}

extern "C" void kernel_launch(void* const* d_in, const int* in_sizes, int n_in,
                              void* d_out, int out_size)
{
    const float* x  = (const float*)d_in[0];   // [B*T*C_IN]
    const float* W  = (const float*)d_in[1];   // [C_IN*C_OUT]
    const float* Bv = (const float*)d_in[2];   // [C_IN*C_OUT]
    float* out = (float*)d_out;

    const int n_rows = in_sizes[0] / C_IN;     // 32768

    // 4096 blocks -> ~8 rows each; ~2M resident-eligible threads saturate HBM.
    int blocks = n_rows / 8;
    if (blocks < 1) blocks = 1;
    if (blocks > n_rows) blocks = n_rows;

    real_embedding_kernel<<<blocks, TPB>>>(x, W, Bv, out, n_rows);
}

// round 9
// speedup vs baseline: 1.1659x; 1.1659x over previous
#include <cuda_runtime.h>
#include <cstdint>

// RealEmbedding: out[bt, i*C_OUT + j] = x[bt, i] * W[i, j] + b[i, j]
// B=64, T=512, C_IN=128, C_OUT=16 -> rows = 32768, row_out = 2048 floats.
//
// R8: latency-bound fix. 4-row manual unroll -> 4 independent LDGs in flight
// per thread per iteration (MLP 1 -> 4), batched STG.128, streaming hints
// (__ldcs for read-once x, __stcs for write-once out).

static constexpr int C_IN    = 128;
static constexpr int C_OUT   = 16;
static constexpr int ROW_OUT = C_IN * C_OUT;   // 2048
static constexpr int TPB     = 512;            // C_IN * (C_OUT/4)
static constexpr int UNROLL  = 4;              // rows per inner iteration

__global__ __launch_bounds__(TPB, 4)
void real_embedding_kernel(const float* __restrict__ x,
                           const float* __restrict__ W,
                           const float* __restrict__ Bv,
                           float* __restrict__ out,
                           int n_rows)
{
    const int tid = threadIdx.x;        // 0..511
    const int i   = tid >> 2;           // input channel 0..127
    const int j4  = tid & 3;            // which float4 of the 16 outputs

    // Per-thread constants: one float4 of W and b, loaded once.
    const float4 w4 = __ldg(reinterpret_cast<const float4*>(W  + i * C_OUT + j4 * 4));
    const float4 b4 = __ldg(reinterpret_cast<const float4*>(Bv + i * C_OUT + j4 * 4));

    const int out_off = i * C_OUT + j4 * 4;

    const int n_groups = n_rows >> 2;   // groups of 4 rows (n_rows = 32768, divisible)

    for (int g = blockIdx.x; g < n_groups; g += gridDim.x) {
        const int row0 = g * UNROLL;

        // Phase 1: issue all 4 x-loads back-to-back (independent -> MLP=4).
        float xv[UNROLL];
        #pragma unroll
        for (int k = 0; k < UNROLL; k++)
            xv[k] = __ldcs(x + (size_t)(row0 + k) * C_IN + i);

        // Phase 2: compute all 16 outputs.
        float4 o[UNROLL];
        #pragma unroll
        for (int k = 0; k < UNROLL; k++) {
            o[k].x = fmaf(xv[k], w4.x, b4.x);
            o[k].y = fmaf(xv[k], w4.y, b4.y);
            o[k].z = fmaf(xv[k], w4.z, b4.z);
            o[k].w = fmaf(xv[k], w4.w, b4.w);
        }

        // Phase 3: 4 back-to-back streaming STG.128.
        #pragma unroll
        for (int k = 0; k < UNROLL; k++)
            __stcs(reinterpret_cast<float4*>(out + (size_t)(row0 + k) * ROW_OUT + out_off),
                   o[k]);
    }
}

extern "C" void kernel_launch(void* const* d_in, const int* in_sizes, int n_in,
                              void* d_out, int out_size)
{
    const float* x  = (const float*)d_in[0];   // [B*T*C_IN]
    const float* W  = (const float*)d_in[1];   // [C_IN*C_OUT]
    const float* Bv = (const float*)d_in[2];   // [C_IN*C_OUT]
    float* out = (float*)d_out;

    const int n_rows   = in_sizes[0] / C_IN;   // 32768
    const int n_groups = (n_rows + UNROLL - 1) / UNROLL;  // 8192

    // 2 groups (8 rows) per block on the nominal shape; full occupancy on 148 SMs.
    int blocks = (n_groups + 1) / 2;
    if (blocks < 1) blocks = 1;
    if (blocks > n_groups) blocks = n_groups;

    real_embedding_kernel<<<blocks, TPB>>>(x, W, Bv, out, n_rows);
}